// round 1
// baseline (speedup 1.0000x reference)
#include <cuda_runtime.h>
#include <math.h>

// Problem constants
#define Bc   2
#define Mc   2048
#define Dc   1024
#define Hc   16
#define DHc  64
#define FFc  2624
#define ROWS (Bc * Mc)      // 4096
#define QKVN (3 * Dc)       // 3072
#define WIN  (2 * FFc)      // 5248

// ---------------- scratch (device globals; no cudaMalloc allowed) ----------------
__device__ __align__(16) float g_xn  [ROWS * Dc];
__device__ __align__(16) float g_qkv [ROWS * QKVN];
__device__ __align__(16) float g_attn[ROWS * Dc];
__device__ __align__(16) float g_x1  [ROWS * Dc];
__device__ __align__(16) float g_h   [ROWS * Dc];
__device__ __align__(16) float g_g   [(size_t)ROWS * WIN];
__device__ __align__(16) float g_act [(size_t)ROWS * FFc];

// ---------------- LayerNorm: one block per row, D=1024, 256 threads ----------------
__global__ void __launch_bounds__(256) ln_kernel(const float* __restrict__ x,
                                                 const float* __restrict__ w,
                                                 const float* __restrict__ b,
                                                 float* __restrict__ out) {
    int row = blockIdx.x;
    int t = threadIdx.x;
    const float4* xr = reinterpret_cast<const float4*>(x + (size_t)row * Dc);
    float4 v = xr[t];
    float s  = v.x + v.y + v.z + v.w;
    float ss = v.x * v.x + v.y * v.y + v.z * v.z + v.w * v.w;

    __shared__ float red0[8], red1[8];
    #pragma unroll
    for (int o = 16; o; o >>= 1) {
        s  += __shfl_xor_sync(0xffffffffu, s,  o);
        ss += __shfl_xor_sync(0xffffffffu, ss, o);
    }
    int wid = t >> 5, lid = t & 31;
    if (lid == 0) { red0[wid] = s; red1[wid] = ss; }
    __syncthreads();
    if (t == 0) {
        float a = 0.f, c = 0.f;
        #pragma unroll
        for (int i = 0; i < 8; i++) { a += red0[i]; c += red1[i]; }
        red0[0] = a; red1[0] = c;
    }
    __syncthreads();
    s = red0[0]; ss = red1[0];
    float mu   = s * (1.0f / Dc);
    float var  = ss * (1.0f / Dc) - mu * mu;
    float rstd = rsqrtf(var + 1e-5f);

    const float4* w4 = reinterpret_cast<const float4*>(w);
    const float4* b4 = reinterpret_cast<const float4*>(b);
    float4 ww = w4[t], bb = b4[t], o4;
    o4.x = (v.x - mu) * rstd * ww.x + bb.x;
    o4.y = (v.y - mu) * rstd * ww.y + bb.y;
    o4.z = (v.z - mu) * rstd * ww.z + bb.z;
    o4.w = (v.w - mu) * rstd * ww.w + bb.w;
    reinterpret_cast<float4*>(out + (size_t)row * Dc)[t] = o4;
}

// ---------------- NT SGEMM: C[M,N] = A[M,K] @ B[N,K]^T (+bias)(+res) ----------------
// BM=BN=128, BK=16, 256 threads, 8x8 per thread. All dims divisible (asserted by shapes).
__global__ void __launch_bounds__(256) gemm_nt(const float* __restrict__ A,
                                               const float* __restrict__ Bw,
                                               const float* __restrict__ bias,
                                               const float* __restrict__ res,
                                               float* __restrict__ C,
                                               int Nd, int Kd) {
    __shared__ __align__(16) float As[16][128];
    __shared__ __align__(16) float Bs[16][128];

    int n0 = blockIdx.x * 128;
    int m0 = blockIdx.y * 128;
    int t  = threadIdx.x;
    int tx = t & 15, ty = t >> 4;

    int lrow = t >> 1;           // 0..127
    int lcol = (t & 1) * 8;      // 0 or 8 (float offset into the 16-wide k slab)

    const float* Ap = A  + (size_t)(m0 + lrow) * Kd + lcol;
    const float* Bp = Bw + (size_t)(n0 + lrow) * Kd + lcol;

    float acc[8][8];
    #pragma unroll
    for (int r = 0; r < 8; r++)
        #pragma unroll
        for (int c = 0; c < 8; c++) acc[r][c] = 0.f;

    for (int k0 = 0; k0 < Kd; k0 += 16) {
        float4 a0 = *reinterpret_cast<const float4*>(Ap + k0);
        float4 a1 = *reinterpret_cast<const float4*>(Ap + k0 + 4);
        float4 b0 = *reinterpret_cast<const float4*>(Bp + k0);
        float4 b1 = *reinterpret_cast<const float4*>(Bp + k0 + 4);
        __syncthreads();
        As[lcol + 0][lrow] = a0.x; As[lcol + 1][lrow] = a0.y;
        As[lcol + 2][lrow] = a0.z; As[lcol + 3][lrow] = a0.w;
        As[lcol + 4][lrow] = a1.x; As[lcol + 5][lrow] = a1.y;
        As[lcol + 6][lrow] = a1.z; As[lcol + 7][lrow] = a1.w;
        Bs[lcol + 0][lrow] = b0.x; Bs[lcol + 1][lrow] = b0.y;
        Bs[lcol + 2][lrow] = b0.z; Bs[lcol + 3][lrow] = b0.w;
        Bs[lcol + 4][lrow] = b1.x; Bs[lcol + 5][lrow] = b1.y;
        Bs[lcol + 6][lrow] = b1.z; Bs[lcol + 7][lrow] = b1.w;
        __syncthreads();

        #pragma unroll
        for (int k = 0; k < 16; k++) {
            float ar[8], br[8];
            *reinterpret_cast<float4*>(ar)     = *reinterpret_cast<float4*>(&As[k][ty * 8]);
            *reinterpret_cast<float4*>(ar + 4) = *reinterpret_cast<float4*>(&As[k][ty * 8 + 4]);
            *reinterpret_cast<float4*>(br)     = *reinterpret_cast<float4*>(&Bs[k][tx * 8]);
            *reinterpret_cast<float4*>(br + 4) = *reinterpret_cast<float4*>(&Bs[k][tx * 8 + 4]);
            #pragma unroll
            for (int r = 0; r < 8; r++)
                #pragma unroll
                for (int c = 0; c < 8; c++) acc[r][c] += ar[r] * br[c];
        }
    }

    float bv[8];
    #pragma unroll
    for (int c = 0; c < 8; c++) bv[c] = bias ? bias[n0 + tx * 8 + c] : 0.f;

    #pragma unroll
    for (int r = 0; r < 8; r++) {
        int gm = m0 + ty * 8 + r;
        float* Cp = C + (size_t)gm * Nd + n0 + tx * 8;
        const float* Rp = res ? (res + (size_t)gm * Nd + n0 + tx * 8) : nullptr;
        #pragma unroll
        for (int c = 0; c < 8; c++) {
            float v = acc[r][c] + bv[c];
            if (res) v += Rp[c];
            Cp[c] = v;
        }
    }
}

// ---------------- RoPE (in-place on q,k slabs of qkv) ----------------
__global__ void rope_kernel(float* __restrict__ qkv) {
    int idx = blockIdx.x * blockDim.x + threadIdx.x;   // ROWS*H*32
    if (idx >= ROWS * Hc * (DHc / 2)) return;
    int j   = idx & 31;
    int h   = (idx >> 5) & (Hc - 1);
    int row = idx >> 9;
    int m   = row & (Mc - 1);

    float inv_freq = powf(10000.0f, -(float)(2 * j) / (float)DHc);
    float freq = (float)m * inv_freq;
    float sn, cs;
    sincosf(freq, &sn, &cs);

    float* qp = qkv + (size_t)row * QKVN + h * DHc;
    float* kp = qp + Dc;
    float q1 = qp[j], q2 = qp[32 + j];
    qp[j]      = q1 * cs - q2 * sn;
    qp[32 + j] = q1 * sn + q2 * cs;
    float k1 = kp[j], k2 = kp[32 + j];
    kp[j]      = k1 * cs - k2 * sn;
    kp[32 + j] = k1 * sn + k2 * cs;
}

// ---------------- Flash attention: 32 queries/block, 64-key tiles, online softmax ----------------
#define QT 32
#define KT 64
// dynamic smem layout (floats):
//   Qs[32][65], Ks[64][65], Vs[64][64], Pb[32][65], m[32], l[32], scale[32], msk[64](int)
#define SM_QS   0
#define SM_KS   (SM_QS + QT * 65)
#define SM_VS   (SM_KS + KT * 65)
#define SM_PB   (SM_VS + KT * 64)
#define SM_M    (SM_PB + QT * 65)
#define SM_L    (SM_M + QT)
#define SM_SC   (SM_L + QT)
#define SM_MSK  (SM_SC + QT)
#define SM_FLOATS (SM_MSK + KT)
#define ATTN_SMEM_BYTES (SM_FLOATS * 4)

__global__ void __launch_bounds__(256) attn_kernel(const float* __restrict__ qkv,
                                                   const int* __restrict__ mask,
                                                   float* __restrict__ out) {
    extern __shared__ float sh[];
    float* Qs = sh + SM_QS;
    float* Ks = sh + SM_KS;
    float* Vs = sh + SM_VS;
    float* Pb = sh + SM_PB;
    float* smM = sh + SM_M;
    float* smL = sh + SM_L;
    float* smS = sh + SM_SC;
    int*   msk = reinterpret_cast<int*>(sh + SM_MSK);

    int m0 = blockIdx.x * QT;
    int h  = blockIdx.y;
    int b  = blockIdx.z;
    int t  = threadIdx.x;

    const float* qbase = qkv + (size_t)(b * Mc + m0) * QKVN + h * DHc;
    const float* kbase = qkv + (size_t)(b * Mc) * QKVN + Dc + h * DHc;
    const float* vbase = kbase + Dc;
    const int*   mbase = mask + b * Mc;

    // load Q (pre-scaled by 1/sqrt(DH))
    for (int idx = t; idx < QT * DHc; idx += 256) {
        int q = idx >> 6, d = idx & 63;
        Qs[q * 65 + d] = qbase[(size_t)q * QKVN + d] * 0.125f;
    }
    if (t < QT) { smM[t] = -1e30f; smL[t] = 0.f; }

    int q  = t >> 3;   // 0..31
    int kg = t & 7;    // also used as dim-group in PV phase
    float o[8];
    #pragma unroll
    for (int j = 0; j < 8; j++) o[j] = 0.f;

    for (int n0 = 0; n0 < Mc; n0 += KT) {
        __syncthreads();  // previous PV phase done with Ks/Vs/Pb
        for (int idx = t; idx < KT * DHc; idx += 256) {
            int kk = idx >> 6, d = idx & 63;
            Ks[kk * 65 + d] = kbase[(size_t)(n0 + kk) * QKVN + d];
            Vs[kk * 64 + d] = vbase[(size_t)(n0 + kk) * QKVN + d];
        }
        if (t < KT) msk[t] = mbase[n0 + t];
        __syncthreads();

        // ---- scores for keys k = kg + 8*i ----
        float s[8];
        #pragma unroll
        for (int i = 0; i < 8; i++) s[i] = 0.f;
        #pragma unroll
        for (int d = 0; d < DHc; d++) {
            float qv = Qs[q * 65 + d];
            #pragma unroll
            for (int i = 0; i < 8; i++) s[i] += qv * Ks[(kg + 8 * i) * 65 + d];
        }
        bool valid[8];
        float mx = -1e30f;
        #pragma unroll
        for (int i = 0; i < 8; i++) {
            valid[i] = (msk[kg + 8 * i] != 0);
            if (valid[i]) mx = fmaxf(mx, s[i]);
        }
        mx = fmaxf(mx, __shfl_xor_sync(0xffffffffu, mx, 1));
        mx = fmaxf(mx, __shfl_xor_sync(0xffffffffu, mx, 2));
        mx = fmaxf(mx, __shfl_xor_sync(0xffffffffu, mx, 4));

        float m_old = smM[q];
        float m_new = fmaxf(m_old, mx);
        float scale = __expf(m_old - m_new);
        float psum = 0.f;
        #pragma unroll
        for (int i = 0; i < 8; i++) {
            float p = valid[i] ? __expf(s[i] - m_new) : 0.f;
            Pb[q * 65 + kg + 8 * i] = p;
            psum += p;
        }
        psum += __shfl_xor_sync(0xffffffffu, psum, 1);
        psum += __shfl_xor_sync(0xffffffffu, psum, 2);
        psum += __shfl_xor_sync(0xffffffffu, psum, 4);
        if (kg == 0) {
            smL[q] = smL[q] * scale + psum;
            smM[q] = m_new;
            smS[q] = scale;
        }
        __syncthreads();

        // ---- PV: thread (q, dg=kg) owns dims d = dg + 8*j ----
        float sc = smS[q];
        #pragma unroll
        for (int j = 0; j < 8; j++) o[j] *= sc;
        for (int kk = 0; kk < KT; kk++) {
            float p = Pb[q * 65 + kk];
            #pragma unroll
            for (int j = 0; j < 8; j++) o[j] += p * Vs[kk * 64 + kg + 8 * j];
        }
    }
    __syncthreads();
    float inv_l = 1.0f / smL[q];
    float* op = out + (size_t)(b * Mc + m0 + q) * Dc + h * DHc;
    #pragma unroll
    for (int j = 0; j < 8; j++) op[kg + 8 * j] = o[j] * inv_l;
}

// ---------------- GeGLU (exact gelu * gate) ----------------
__global__ void geglu_kernel(const float* __restrict__ g, float* __restrict__ act) {
    int idx = blockIdx.x * blockDim.x + threadIdx.x;
    if (idx >= ROWS * FFc) return;
    int r = idx / FFc;
    int j = idx - r * FFc;
    float x    = g[(size_t)r * WIN + j];
    float gate = g[(size_t)r * WIN + FFc + j];
    float ge = 0.5f * x * (1.0f + erff(x * 0.7071067811865476f));
    act[idx] = ge * gate;
}

// ---------------- launch ----------------
extern "C" void kernel_launch(void* const* d_in, const int* in_sizes, int n_in,
                              void* d_out, int out_size) {
    const float* x     = (const float*)d_in[0];
    const int*   mask  = (const int*)  d_in[1];
    const float* ln1w  = (const float*)d_in[2];
    const float* ln1b  = (const float*)d_in[3];
    const float* wqkv  = (const float*)d_in[4];
    const float* bqkv  = (const float*)d_in[5];
    const float* wo    = (const float*)d_in[6];
    const float* ln2w  = (const float*)d_in[7];
    const float* ln2b  = (const float*)d_in[8];
    const float* wi    = (const float*)d_in[9];
    const float* womlp = (const float*)d_in[10];
    float* out = (float*)d_out;

    float *xn, *qkvb, *attn, *x1, *hb, *gb, *actb;
    cudaGetSymbolAddress((void**)&xn,   g_xn);
    cudaGetSymbolAddress((void**)&qkvb, g_qkv);
    cudaGetSymbolAddress((void**)&attn, g_attn);
    cudaGetSymbolAddress((void**)&x1,   g_x1);
    cudaGetSymbolAddress((void**)&hb,   g_h);
    cudaGetSymbolAddress((void**)&gb,   g_g);
    cudaGetSymbolAddress((void**)&actb, g_act);

    cudaFuncSetAttribute(attn_kernel, cudaFuncAttributeMaxDynamicSharedMemorySize,
                         ATTN_SMEM_BYTES);

    // 1. LN1
    ln_kernel<<<ROWS, 256>>>(x, ln1w, ln1b, xn);
    // 2. QKV projection (+bias)
    gemm_nt<<<dim3(QKVN / 128, ROWS / 128), 256>>>(xn, wqkv, bqkv, nullptr, qkvb, QKVN, Dc);
    // 3. RoPE
    rope_kernel<<<(ROWS * Hc * (DHc / 2) + 255) / 256, 256>>>(qkvb);
    // 4. Attention
    attn_kernel<<<dim3(Mc / QT, Hc, Bc), 256, ATTN_SMEM_BYTES>>>(qkvb, mask, attn);
    // 5. WO projection + residual(x)
    gemm_nt<<<dim3(Dc / 128, ROWS / 128), 256>>>(attn, wo, nullptr, x, x1, Dc, Dc);
    // 6. LN2
    ln_kernel<<<ROWS, 256>>>(x1, ln2w, ln2b, hb);
    // 7. WI projection
    gemm_nt<<<dim3(WIN / 128, ROWS / 128), 256>>>(hb, wi, nullptr, nullptr, gb, WIN, Dc);
    // 8. GeGLU
    geglu_kernel<<<(ROWS * FFc + 255) / 256, 256>>>(gb, actb);
    // 9. WO_MLP projection + residual(x1) -> out
    gemm_nt<<<dim3(Dc / 128, ROWS / 128), 256>>>(actb, womlp, nullptr, x1, out, Dc, FFc);
}